// round 1
// baseline (speedup 1.0000x reference)
#include <cuda_runtime.h>

// VectorQuantizer: z_e [32,64,32,32] f32, emb [1024,64] f32
// Outputs (concatenated f32): z_st [32,64,32,32] (2097152), loss (1),
// perplexity (1), encodings [32768,1024] (33554432). Total 35651586.

#define NB 32
#define ND 64
#define NH 32
#define NW 32
#define NK 1024
#define HW (NH * NW)                 // 1024
#define NN (NB * NH * NW)            // 32768 rows
#define ZELEMS (NB * ND * NH * NW)   // 2097152
#define TK 128                        // K tile held in smem
#define AT 256                        // threads in argmin block
#define NBLK (NN / AT)               // 128 blocks

__device__ int    g_idx[NN];
__device__ int    g_counts[NK];
__device__ float  g_e2[NK];
__device__ double g_losspart[NBLK];

static __device__ __forceinline__ unsigned long long pk2(float lo, float hi) {
    unsigned long long r;
    asm("mov.b64 %0, {%1, %2};" : "=l"(r) : "f"(lo), "f"(hi));
    return r;
}
static __device__ __forceinline__ void upk2(unsigned long long v, float& lo, float& hi) {
    asm("mov.b64 {%0, %1}, %2;" : "=f"(lo), "=f"(hi) : "l"(v));
}
// packed f32x2 FMA: acc.{lo,hi} += a.{lo,hi} * b.{lo,hi}
static __device__ __forceinline__ void fma2(unsigned long long& acc,
                                            unsigned long long a,
                                            unsigned long long b) {
    asm("fma.rn.f32x2 %0, %1, %2, %0;" : "+l"(acc) : "l"(a), "l"(b));
}

// ---------------------------------------------------------------------------
// prep: zero counts, precompute ||e_k||^2 (fp64 accumulate -> fp32)
// ---------------------------------------------------------------------------
__global__ void vq_prep(const float* __restrict__ emb) {
    int k = threadIdx.x;  // 1024 threads
    g_counts[k] = 0;
    const float* e = emb + (size_t)k * ND;
    double s = 0.0;
#pragma unroll
    for (int d = 0; d < ND; d++) {
        double v = (double)e[d];
        s += v * v;
    }
    g_e2[k] = (float)s;
}

// ---------------------------------------------------------------------------
// argmin + z_st + loss partials + counts
// One thread per row n. x kept as 32 packed f32x2 registers (D pairs).
// emb K-tile staged in smem; inner dot uses fma.rn.f32x2 (2 chains for ILP).
// dist combine replicates reference rounding: (a + b_k) - 2*dot.
// Tie-break: strictly-less keeps lowest k (jnp.argmin semantics).
// ---------------------------------------------------------------------------
__global__ __launch_bounds__(AT) void vq_argmin(const float* __restrict__ ze,
                                                const float* __restrict__ emb,
                                                float* __restrict__ out) {
    __shared__ float  tile[TK * ND];   // 32 KB
    __shared__ float  e2s[TK];
    __shared__ double red[AT];

    const int tid = threadIdx.x;
    const int n   = blockIdx.x * AT + tid;
    const int b   = n >> 10;          // n / HW
    const int hw  = n & (HW - 1);

    const float* zp = ze + (size_t)b * ND * HW + hw;  // stride HW between d's

    unsigned long long xp[ND / 2];
    double s64 = 0.0;
#pragma unroll
    for (int i = 0; i < ND / 2; i++) {
        float x0 = zp[(size_t)(2 * i) * HW];
        float x1 = zp[(size_t)(2 * i + 1) * HW];
        xp[i] = pk2(x0, x1);
        s64 += (double)x0 * (double)x0 + (double)x1 * (double)x1;
    }
    const float a = (float)s64;   // ||x||^2 (binade-constant offset vs ref: argmin-invariant)

    float best  = 3.4e38f;
    int   bestk = 0;

    for (int kt = 0; kt < NK; kt += TK) {
        // cooperative tile load (coalesced float4)
        const float4* src = (const float4*)(emb + (size_t)kt * ND);
        float4*       dst = (float4*)tile;
        for (int i = tid; i < TK * ND / 4; i += AT) dst[i] = src[i];
        if (tid < TK) e2s[tid] = g_e2[kt + tid];
        __syncthreads();

#pragma unroll 4
        for (int kk = 0; kk < TK; kk++) {
            const unsigned long long* es =
                (const unsigned long long*)(tile + kk * ND);
            unsigned long long a0 = 0ULL, a1 = 0ULL;
#pragma unroll
            for (int j = 0; j < ND / 2; j += 2) {
                fma2(a0, xp[j],     es[j]);
                fma2(a1, xp[j + 1], es[j + 1]);
            }
            float l0, h0, l1, h1;
            upk2(a0, l0, h0);
            upk2(a1, l1, h1);
            float dot  = (l0 + h0) + (l1 + h1);
            float dist = (a + e2s[kk]) - 2.0f * dot;   // reference combine order
            if (dist < best) { best = dist; bestk = kt + kk; }
        }
        __syncthreads();
    }

    g_idx[n] = bestk;
    atomicAdd(&g_counts[bestk], 1);

    // epilogue: z_st = z + (z_q - z) with both fp32 roundings; loss partial fp64
    const float* eq = emb + (size_t)bestk * ND;
    float*       op = out + (size_t)b * ND * HW + hw;
    double ls = 0.0;
#pragma unroll
    for (int i = 0; i < ND / 2; i++) {
        float x0, x1;
        upk2(xp[i], x0, x1);
        float q0 = eq[2 * i], q1 = eq[2 * i + 1];
        float d0 = q0 - x0,   d1 = q1 - x1;
        op[(size_t)(2 * i) * HW]     = x0 + d0;
        op[(size_t)(2 * i + 1) * HW] = x1 + d1;
        float s0 = d0 * d0, s1 = d1 * d1;   // square in fp32 like reference
        ls += (double)s0 + (double)s1;
    }

    // deterministic block reduction of loss partials
    red[tid] = ls;
    __syncthreads();
    for (int st = AT / 2; st > 0; st >>= 1) {
        if (tid < st) red[tid] += red[tid + st];
        __syncthreads();
    }
    if (tid == 0) g_losspart[blockIdx.x] = red[0];
}

// ---------------------------------------------------------------------------
// one-hot encodings: one block per row, float2 stores (base offset is only
// 8B-aligned because of the 2 leading scalars), fused "1" insertion.
// ---------------------------------------------------------------------------
__global__ void vq_enc(float* __restrict__ enc) {
    const int n   = blockIdx.x;
    const int idx = g_idx[n];
    float2* row = (float2*)(enc + (size_t)n * NK);
    const int h = idx >> 1;      // which float2
    const int r = idx & 1;       // which component
    const int t = threadIdx.x;   // 256 threads, 512 float2 per row
#pragma unroll
    for (int i = t; i < NK / 2; i += 256) {
        float2 v = make_float2(0.0f, 0.0f);
        if (i == h) { if (r) v.y = 1.0f; else v.x = 1.0f; }
        row[i] = v;
    }
}

// ---------------------------------------------------------------------------
// finalize: loss and perplexity scalars
// ---------------------------------------------------------------------------
__global__ void vq_fin(float* __restrict__ out) {
    __shared__ double sred[NK];
    const int t = threadIdx.x;  // 1024 threads
    float p    = (float)g_counts[t] / (float)NN;   // exact (count / 2^15)
    float term = p * logf(p + 1e-10f);
    sred[t] = (double)term;
    __syncthreads();
    for (int st = NK / 2; st > 0; st >>= 1) {
        if (t < st) sred[t] += sred[t + st];
        __syncthreads();
    }
    if (t == 0) {
        double s = 0.0;
        for (int i = 0; i < NBLK; i++) s += g_losspart[i];  // deterministic order
        float m = (float)(s / (double)ZELEMS);              // q_latent == e_latent
        out[ZELEMS]     = m + 0.25f * m;                    // loss
        out[ZELEMS + 1] = expf(-(float)sred[0]);            // perplexity
    }
}

extern "C" void kernel_launch(void* const* d_in, const int* in_sizes, int n_in,
                              void* d_out, int out_size) {
    const float* ze  = (const float*)d_in[0];
    const float* emb = (const float*)d_in[1];
    float*       out = (float*)d_out;

    vq_prep<<<1, NK>>>(emb);
    vq_argmin<<<NBLK, AT>>>(ze, emb, out);
    vq_enc<<<NN, 256>>>(out + (size_t)ZELEMS + 2);
    vq_fin<<<1, NK>>>(out);
}

// round 4
// speedup vs baseline: 2.8566x; 2.8566x over previous
#include <cuda_runtime.h>

// VectorQuantizer: z_e [32,64,32,32] f32, emb [1024,64] f32
// out (f32): z_st [2097152], loss, perplexity, encodings [32768*1024]

#define ND 64
#define NK 1024
#define NH 32
#define NW 32
#define NB 32
#define HW (NH * NW)                  // 1024
#define NN (NB * HW)                  // 32768 rows
#define ZELEMS (NB * ND * HW)         // 2097152
#define EPI_BLOCKS (NN / 256)         // 128

__device__ unsigned long long g_embdup[ND * NK];  // [d][k] = (e_{k,d}, e_{k,d})
__device__ float              g_e2[NK];
__device__ float              g_a[NN];            // ||x_n||^2 (fp32)
__device__ unsigned long long g_best[NN];         // (dist_bits<<32)|code
__device__ int                g_idx[NN];
__device__ int                g_counts[NK];
__device__ double             g_losspart[EPI_BLOCKS];

static __device__ __forceinline__ unsigned long long pk2(float lo, float hi) {
    unsigned long long r;
    asm("mov.b64 %0, {%1, %2};" : "=l"(r) : "f"(lo), "f"(hi));
    return r;
}
static __device__ __forceinline__ void upk2(unsigned long long v, float& lo, float& hi) {
    asm("mov.b64 {%0, %1}, %2;" : "=f"(lo), "=f"(hi) : "l"(v));
}
static __device__ __forceinline__ void fma2(unsigned long long& acc,
                                            unsigned long long a,
                                            unsigned long long b) {
    asm("fma.rn.f32x2 %0, %1, %2, %0;" : "+l"(acc) : "l"(a), "l"(b));
}
static __device__ __forceinline__ unsigned long long umin64(unsigned long long a,
                                                            unsigned long long b) {
    return a < b ? a : b;
}

// ---------------------------------------------------------------------------
// prep: build duplicated-transposed emb table, e2, row sumsq, init best/counts
// grid 256 x 256 = 65536 threads
// ---------------------------------------------------------------------------
__global__ void vq_prep(const float* __restrict__ ze, const float* __restrict__ emb) {
    const int t = blockIdx.x * 256 + threadIdx.x;       // 0..65535
    const int d = t >> 10, k = t & (NK - 1);
    const float e = emb[k * ND + d];
    g_embdup[t] = pk2(e, e);                            // write-coalesced

    if (t < NK) {
        g_counts[t] = 0;
        const float* er = emb + t * ND;
        double s = 0.0;
#pragma unroll
        for (int i = 0; i < ND; i++) { double v = (double)er[i]; s += v * v; }
        g_e2[t] = (float)s;
    }
    if (t < NN) {
        g_best[t] = 0xFFFFFFFFFFFFFFFFULL;
        const int b = t >> 10, hw = t & (HW - 1);
        const float* zp = ze + (size_t)b * ND * HW + hw;
        double s = 0.0;
#pragma unroll
        for (int i = 0; i < ND; i++) { double v = (double)zp[(size_t)i * HW]; s += v * v; }
        g_a[t] = (float)s;                              // integer-ULP offset vs ref: argmin-invariant
    }
}

// ---------------------------------------------------------------------------
// argmin GEMM: block = 64 rows x 256 codes, thread = 8 rows x 8 codes.
// acc packed f32x2 over row pairs; b from pre-duplicated L2-resident table.
// grid (512, 4) x 256 threads
// ---------------------------------------------------------------------------
__global__ __launch_bounds__(256, 2) void vq_argmin(const float* __restrict__ ze) {
    __shared__ float xs[ND * 64];   // [d][row] 16 KB

    const int tid = threadIdx.x;
    const int w   = tid >> 5;       // rowgroup: rows 8w..8w+7
    const int g   = tid & 31;       // codegroup lane
    const int row0 = blockIdx.x * 64;
    const int b    = row0 >> 10;
    const int hw0  = row0 & (HW - 1);

    // stage x tile: xs[d*64 + r] = ze[b][d][hw0 + r]
    const float* zbase = ze + (size_t)b * ND * HW + hw0;
#pragma unroll
    for (int i = 0; i < 16; i++) {
        const int idx = tid + i * 256;
        const int d = idx >> 6, r = idx & 63;
        xs[idx] = zbase[(size_t)d * HW + r];
    }
    __syncthreads();

    const int cbase = blockIdx.y * 256 + g;             // thread codes: cbase + 32*c
    const unsigned long long* __restrict__ bq = g_embdup + cbase;
    const float* xr = xs + 8 * w;

    unsigned long long acc[4][8];
#pragma unroll
    for (int rp = 0; rp < 4; rp++)
#pragma unroll
        for (int c = 0; c < 8; c++) acc[rp][c] = 0ULL;

#pragma unroll 4
    for (int d = 0; d < ND; d++) {
        unsigned long long av[4], bv[8];
#pragma unroll
        for (int rp = 0; rp < 4; rp++)
            av[rp] = *(const unsigned long long*)(xr + 2 * rp);   // broadcast LDS.64
#pragma unroll
        for (int c = 0; c < 8; c++) bv[c] = bq[32 * c];           // coalesced LDG.64
#pragma unroll
        for (int c = 0; c < 8; c++)
#pragma unroll
            for (int rp = 0; rp < 4; rp++) fma2(acc[rp][c], av[rp], bv[c]);
        xr += 64;
        bq += NK;
    }

    // epilogue: dist = fl(fl(a+e2) - 2*dot), key = (bits<<32)|code, min
    unsigned long long bestk[8];
#pragma unroll
    for (int r = 0; r < 8; r++) bestk[r] = 0xFFFFFFFFFFFFFFFFULL;

#pragma unroll
    for (int rp = 0; rp < 4; rp++) {
        const float a0 = g_a[row0 + 8 * w + 2 * rp];
        const float a1 = g_a[row0 + 8 * w + 2 * rp + 1];
#pragma unroll
        for (int c = 0; c < 8; c++) {
            const int code = cbase + 32 * c;
            const float e2 = g_e2[code];
            float d0, d1;
            upk2(acc[rp][c], d0, d1);
            const float dist0 = fmaf(-2.0f, d0, a0 + e2);
            const float dist1 = fmaf(-2.0f, d1, a1 + e2);
            const unsigned long long k0 =
                ((unsigned long long)__float_as_uint(dist0) << 32) | (unsigned)code;
            const unsigned long long k1 =
                ((unsigned long long)__float_as_uint(dist1) << 32) | (unsigned)code;
            bestk[2 * rp]     = umin64(bestk[2 * rp], k0);
            bestk[2 * rp + 1] = umin64(bestk[2 * rp + 1], k1);
        }
    }
    // warp reduce (all lanes hold the same 8 rows)
#pragma unroll
    for (int off = 16; off > 0; off >>= 1) {
#pragma unroll
        for (int r = 0; r < 8; r++) {
            const unsigned long long o = __shfl_down_sync(0xFFFFFFFFu, bestk[r], off);
            bestk[r] = umin64(bestk[r], o);
        }
    }
    if (g == 0) {
#pragma unroll
        for (int r = 0; r < 8; r++)
            atomicMin(&g_best[row0 + 8 * w + r], bestk[r]);
    }
}

// ---------------------------------------------------------------------------
// epilogue: idx, counts, z_st, loss partials. grid 128 x 256
// ---------------------------------------------------------------------------
__global__ __launch_bounds__(256) void vq_epi(const float* __restrict__ ze,
                                              const float* __restrict__ emb,
                                              float* __restrict__ out) {
    __shared__ double red[256];
    const int tid = threadIdx.x;
    const int n = blockIdx.x * 256 + tid;
    const int b = n >> 10, hw = n & (HW - 1);

    const int idx = (int)(g_best[n] & 0xFFFFFFFFULL);
    g_idx[n] = idx;
    atomicAdd(&g_counts[idx], 1);

    const float* zp = ze + (size_t)b * ND * HW + hw;
    const float* eq = emb + (size_t)idx * ND;
    float* op = out + (size_t)b * ND * HW + hw;
    double ls = 0.0;
#pragma unroll
    for (int d = 0; d < ND; d++) {
        const float x = zp[(size_t)d * HW];
        const float q = eq[d];
        const float df = q - x;
        op[(size_t)d * HW] = x + df;            // z + (z_q - z), both fp32 roundings
        const float s = df * df;
        ls += (double)s;
    }
    red[tid] = ls;
    __syncthreads();
    for (int st = 128; st > 0; st >>= 1) {
        if (tid < st) red[tid] += red[tid + st];
        __syncthreads();
    }
    if (tid == 0) g_losspart[blockIdx.x] = red[0];
}

// ---------------------------------------------------------------------------
// one-hot encodings: block per row, float2 stores (base only 8B-aligned)
// ---------------------------------------------------------------------------
__global__ void vq_enc(float* __restrict__ enc) {
    const int n = blockIdx.x;
    const int idx = g_idx[n];
    float2* row = (float2*)(enc + (size_t)n * NK);
    const int h = idx >> 1, r = idx & 1;
    const int t = threadIdx.x;
#pragma unroll
    for (int i = t; i < NK / 2; i += 256) {
        float2 v = make_float2(0.0f, 0.0f);
        if (i == h) { if (r) v.y = 1.0f; else v.x = 1.0f; }
        row[i] = v;
    }
}

// ---------------------------------------------------------------------------
// finalize: loss + perplexity. 1 x 256
// ---------------------------------------------------------------------------
__global__ void vq_fin(float* __restrict__ out) {
    __shared__ double se[256];
    __shared__ double sl[256];
    const int t = threadIdx.x;
    double ent = 0.0;
#pragma unroll
    for (int i = 0; i < 4; i++) {
        const int k = t + 256 * i;
        const float p = (float)g_counts[k] / (float)NN;
        ent += (double)(p * logf(p + 1e-10f));
    }
    se[t] = ent;
    sl[t] = (t < EPI_BLOCKS) ? g_losspart[t] : 0.0;
    __syncthreads();
    for (int st = 128; st > 0; st >>= 1) {
        if (t < st) { se[t] += se[t + st]; sl[t] += sl[t + st]; }
        __syncthreads();
    }
    if (t == 0) {
        const float m = (float)(sl[0] / (double)ZELEMS);  // q_latent == e_latent
        out[ZELEMS]     = m + 0.25f * m;
        out[ZELEMS + 1] = expf(-(float)se[0]);
    }
}

extern "C" void kernel_launch(void* const* d_in, const int* in_sizes, int n_in,
                              void* d_out, int out_size) {
    const float* ze  = (const float*)d_in[0];
    const float* emb = (const float*)d_in[1];
    float*       out = (float*)d_out;

    vq_prep<<<256, 256>>>(ze, emb);
    vq_argmin<<<dim3(NN / 64, NK / 256), 256>>>(ze);
    vq_epi<<<EPI_BLOCKS, 256>>>(ze, emb, out);
    vq_enc<<<NN, 256>>>(out + (size_t)ZELEMS + 2);
    vq_fin<<<1, 256>>>(out);
}